// round 9
// baseline (speedup 1.0000x reference)
#include <cuda_runtime.h>
#include <cuda_bf16.h>
#include <math.h>

// GCN: N<=100000, E<=1280000, 18 -> 32 -> 64 -> 2, log_softmax.
// Slot-CSR (deg<=64 for Poisson(12.8) input). Pipeline:
//   memset(cursor) -> scatter -> meta+xw1 -> agg1(32-dim gather) ->
//   agg2t(32-dim gather, t = di*agg stored into g_p) ->
//   tail(dense: relu(t@W2+b2) @ Wfc + log_softmax)
// Both gathers are 32-dim (128B/edge). The W2 transform + FC run as ONE
// dense tiled kernel on the aggregated t (reads 12.8MB, writes 0.8MB).

#define MAXN 100000
#define SLOT_SHIFT 6
#define FULL 0xffffffffu

__device__ int    g_cursor[MAXN];          // zeroed, becomes degree after scatter
__device__ int    g_csr[MAXN << SLOT_SHIFT];
__device__ float2 g_meta[MAXN];            // (dinv, bitcast deg)
__device__ float  g_p [MAXN * 32];         // dinv*(x@W1); later reused for t
__device__ float  g_hs[MAXN * 32];         // dinv[i] * relu(layer1)[i]

// ---------------- scatter edges into slot-CSR ----------------

__global__ void k_scatter(const int* __restrict__ src, const int* __restrict__ dst, int e) {
    int i = blockIdx.x * blockDim.x + threadIdx.x;
    if (i < e) {
        int d = dst[i];
        int p = atomicAdd(&g_cursor[d], 1);
        g_csr[(d << SLOT_SHIFT) + p] = src[i];
    }
}

// ---------- meta (dinv,deg) + xw1 pre-scaled: g_p = dinv * (x @ W1) ----------

__global__ void __launch_bounds__(256) k_meta_xw1(const float* __restrict__ x,
                                                  const float* __restrict__ W1, int n) {
    __shared__ float sW1[18 * 32];
    __shared__ float sdinv[256];
    for (int i = threadIdx.x; i < 18 * 32; i += blockDim.x) sW1[i] = W1[i];

    int t  = threadIdx.x;
    int i0 = blockIdx.x * 256;
    int i  = i0 + t;
    float di = 0.f;
    if (i < n) {
        int d = g_cursor[i];
        di = rsqrtf((float)(d + 1));            // +1 self loop
        g_meta[i] = make_float2(di, __int_as_float(d));
    }
    sdinv[t] = di;
    __syncthreads();

    int lane = t & 31;
    int w    = t >> 5;
    int base = i0 + w * 32;
    #pragma unroll 1
    for (int q = 0; q < 32; q++) {
        int node = base + q;
        if (node >= n) break;
        float xv = (lane < 18) ? __ldg(&x[node * 18 + lane]) : 0.f;
        float acc = 0.f;
        #pragma unroll
        for (int k = 0; k < 18; k++) {
            float xk = __shfl_sync(FULL, xv, k);
            acc = fmaf(xk, sW1[k * 32 + lane], acc);
        }
        g_p[node * 32 + lane] = sdinv[w * 32 + q] * acc;
    }
}

// ---- agg1 + relu, store pre-scaled:  g_hs = dinv * relu(di*agg(g_p) + b1) ----

__global__ void __launch_bounds__(256) k_agg1(const float* __restrict__ b1, int n) {
    __shared__ float sb1[32];
    if (threadIdx.x < 32) sb1[threadIdx.x] = b1[threadIdx.x];
    __syncthreads();

    int lane = threadIdx.x & 31;
    int warp = (blockIdx.x * blockDim.x + threadIdx.x) >> 5;
    int nw   = (gridDim.x * blockDim.x) >> 5;
    for (int i = warp; i < n; i += nw) {
        float2 meta = g_meta[i];
        float di = meta.x;
        int cnt  = __float_as_int(meta.y);
        const int4* cp4 = (const int4*)(g_csr + (i << SLOT_SHIFT));
        float s0 = g_p[i * 32 + lane];    // self-loop (already di*xw1)
        float s1 = 0.f, s2 = 0.f, s3 = 0.f;
        int cnt4 = cnt >> 2;
        for (int q = 0; q < cnt4; q++) {
            int4 j = __ldg(cp4 + q);
            s0 += __ldg(&g_p[j.x * 32 + lane]);
            s1 += __ldg(&g_p[j.y * 32 + lane]);
            s2 += __ldg(&g_p[j.z * 32 + lane]);
            s3 += __ldg(&g_p[j.w * 32 + lane]);
        }
        int rem = cnt & 3;
        if (rem) {
            int4 j = __ldg(cp4 + cnt4);
            s0 += __ldg(&g_p[j.x * 32 + lane]);
            if (rem > 1) s1 += __ldg(&g_p[j.y * 32 + lane]);
            if (rem > 2) s2 += __ldg(&g_p[j.z * 32 + lane]);
        }
        float s = (s0 + s1) + (s2 + s3);
        float h = fmaxf(fmaf(di, s, sb1[lane]), 0.f);
        g_hs[i * 32 + lane] = di * h;
    }
}

// ---- agg2t: t = di * agg(g_hs), stored into g_p (g_p is dead after agg1) ----

__global__ void __launch_bounds__(256) k_agg2t(int n) {
    int lane = threadIdx.x & 31;
    int warp = (blockIdx.x * blockDim.x + threadIdx.x) >> 5;
    int nw   = (gridDim.x * blockDim.x) >> 5;
    for (int i = warp; i < n; i += nw) {
        float2 meta = g_meta[i];
        float di = meta.x;
        int cnt  = __float_as_int(meta.y);
        const int4* cp4 = (const int4*)(g_csr + (i << SLOT_SHIFT));
        float s0 = g_hs[i * 32 + lane];   // self-loop (already di*h)
        float s1 = 0.f, s2 = 0.f, s3 = 0.f;
        int cnt4 = cnt >> 2;
        for (int q = 0; q < cnt4; q++) {
            int4 j = __ldg(cp4 + q);
            s0 += __ldg(&g_hs[j.x * 32 + lane]);
            s1 += __ldg(&g_hs[j.y * 32 + lane]);
            s2 += __ldg(&g_hs[j.z * 32 + lane]);
            s3 += __ldg(&g_hs[j.w * 32 + lane]);
        }
        int rem = cnt & 3;
        if (rem) {
            int4 j = __ldg(cp4 + cnt4);
            s0 += __ldg(&g_hs[j.x * 32 + lane]);
            if (rem > 1) s1 += __ldg(&g_hs[j.y * 32 + lane]);
            if (rem > 2) s2 += __ldg(&g_hs[j.z * 32 + lane]);
        }
        g_p[i * 32 + lane] = di * ((s0 + s1) + (s2 + s3));
    }
}

// ---- tail: out = log_softmax(relu(t @ W2 + b2) @ Wfc + bfc) ----
// Block = 256 threads, tile = 32 nodes. lane = node-in-tile, warp w owns
// output cols [w*8, w*8+8). Cross-warp FC reduction via smem partials.

__global__ void __launch_bounds__(256) k_tail(const float* __restrict__ W2,
                                              const float* __restrict__ b2,
                                              const float* __restrict__ Wfc,
                                              const float* __restrict__ bfc,
                                              float* __restrict__ out, int n) {
    __shared__ float sW[32 * 64];
    __shared__ float sb2[64];
    __shared__ float sWfc[128];
    __shared__ float sbfc[2];
    __shared__ float sH[32][33];
    __shared__ float sp[8][32][2];
    for (int i = threadIdx.x; i < 32 * 64; i += 256) sW[i] = W2[i];
    if (threadIdx.x < 128) sWfc[threadIdx.x] = Wfc[threadIdx.x];
    if (threadIdx.x < 64)  sb2[threadIdx.x]  = b2[threadIdx.x];
    if (threadIdx.x < 2)   sbfc[threadIdx.x] = bfc[threadIdx.x];

    int lane = threadIdx.x & 31;
    int w    = threadIdx.x >> 5;

    for (int base = blockIdx.x * 32; base < n; base += gridDim.x * 32) {
        __syncthreads();
        // stage 32x32 t tile (1024 floats, 256 threads x float4)
        {
            int fi = threadIdx.x * 4;
            int node = base + (fi >> 5);
            if (node < n) {
                float4 v = *(const float4*)(g_p + base * 32 + fi);
                int r = fi >> 5, c = fi & 31;
                sH[r][c]     = v.x;
                sH[r][c + 1] = v.y;
                sH[r][c + 2] = v.z;
                sH[r][c + 3] = v.w;
            }
        }
        __syncthreads();

        float acc[8] = {0.f, 0.f, 0.f, 0.f, 0.f, 0.f, 0.f, 0.f};
        #pragma unroll 8
        for (int k = 0; k < 32; k++) {
            float v = sH[lane][k];
            const float4* wk = (const float4*)(sW + k * 64 + w * 8);
            float4 w0 = wk[0], w1 = wk[1];
            acc[0] = fmaf(v, w0.x, acc[0]);
            acc[1] = fmaf(v, w0.y, acc[1]);
            acc[2] = fmaf(v, w0.z, acc[2]);
            acc[3] = fmaf(v, w0.w, acc[3]);
            acc[4] = fmaf(v, w1.x, acc[4]);
            acc[5] = fmaf(v, w1.y, acc[5]);
            acc[6] = fmaf(v, w1.z, acc[6]);
            acc[7] = fmaf(v, w1.w, acc[7]);
        }
        // bias + relu + FC partials for this warp's 8 cols
        float p0 = 0.f, p1 = 0.f;
        #pragma unroll
        for (int c = 0; c < 8; c++) {
            float h = fmaxf(acc[c] + sb2[w * 8 + c], 0.f);
            p0 = fmaf(h, sWfc[(w * 8 + c) * 2],     p0);
            p1 = fmaf(h, sWfc[(w * 8 + c) * 2 + 1], p1);
        }
        sp[w][lane][0] = p0;
        sp[w][lane][1] = p1;
        __syncthreads();
        if (w == 0) {
            int node = base + lane;
            if (node < n) {
                float q0 = 0.f, q1 = 0.f;
                #pragma unroll
                for (int ww = 0; ww < 8; ww++) {
                    q0 += sp[ww][lane][0];
                    q1 += sp[ww][lane][1];
                }
                float l0 = q0 + sbfc[0];
                float l1 = q1 + sbfc[1];
                float m  = fmaxf(l0, l1);
                float lse = m + logf(expf(l0 - m) + expf(l1 - m));
                ((float2*)out)[node] = make_float2(l0 - lse, l1 - lse);
            }
        }
    }
}

// ---------------- launch ----------------

extern "C" void kernel_launch(void* const* d_in, const int* in_sizes, int n_in,
                              void* d_out, int out_size) {
    const float* x   = (const float*)d_in[0];
    const int*   ei  = (const int*)d_in[1];
    const float* W1  = (const float*)d_in[2];
    const float* b1  = (const float*)d_in[3];
    const float* W2  = (const float*)d_in[4];
    const float* b2  = (const float*)d_in[5];
    const float* Wfc = (const float*)d_in[6];
    const float* bfc = (const float*)d_in[7];
    float* out = (float*)d_out;

    int n = in_sizes[0] / 18;
    int e = in_sizes[1] / 2;
    const int* src = ei;
    const int* dst = ei + e;

    void* curp = nullptr;
    cudaGetSymbolAddress(&curp, g_cursor);
    cudaMemsetAsync(curp, 0, n * sizeof(int));

    int nb_tail = (n + 31) / 32;
    if (nb_tail > 1184) nb_tail = 1184;

    k_scatter<<<(e + 255) / 256, 256>>>(src, dst, e);
    k_meta_xw1<<<(n + 255) / 256, 256>>>(x, W1, n);
    k_agg1<<<1184, 256>>>(b1, n);
    k_agg2t<<<1184, 256>>>(n);
    k_tail<<<nb_tail, 256>>>(W2, b2, Wfc, bfc, out, n);
}

// round 11
// speedup vs baseline: 1.2368x; 1.2368x over previous
#include <cuda_runtime.h>
#include <cuda_bf16.h>
#include <math.h>

// GCN: N<=100000, E<=1280000, 18 -> 32 -> 64 -> 2, log_softmax.
// Round-6 fused structure (best at 119.3us) + dual-node epilogue in agg2:
// one warp gathers TWO nodes, then one joint W2/FC epilogue where each
// LDS.128 weight read (broadcast-dedup'd) serves both nodes -> 4x less
// smem traffic than the per-node shuffle-GEMV (was 64 wf/node -> 16).
// Slot-CSR (deg<=64, Poisson(12.8)). 4 kernels + 1 memset.
// (Round 10 was an infra failure; this is the round-9 experiment re-run.)

#define MAXN 100000
#define SLOT_SHIFT 6
#define FULL 0xffffffffu

__device__ int    g_cursor[MAXN];          // zeroed, becomes degree after scatter
__device__ int    g_csr[MAXN << SLOT_SHIFT];
__device__ float2 g_meta[MAXN];            // (dinv, bitcast deg)
__device__ float  g_p [MAXN * 32];         // dinv[i] * (x @ W1)[i]
__device__ float  g_hs[MAXN * 32];         // dinv[i] * relu(layer1)[i]

// ---------------- scatter edges into slot-CSR ----------------

__global__ void k_scatter(const int* __restrict__ src, const int* __restrict__ dst, int e) {
    int i = blockIdx.x * blockDim.x + threadIdx.x;
    if (i < e) {
        int d = dst[i];
        int p = atomicAdd(&g_cursor[d], 1);
        g_csr[(d << SLOT_SHIFT) + p] = src[i];
    }
}

// ---------- meta (dinv,deg) + xw1 pre-scaled: g_p = dinv * (x @ W1) ----------

__global__ void __launch_bounds__(256) k_meta_xw1(const float* __restrict__ x,
                                                  const float* __restrict__ W1, int n) {
    __shared__ float sW1[18 * 32];
    __shared__ float sdinv[256];
    for (int i = threadIdx.x; i < 18 * 32; i += blockDim.x) sW1[i] = W1[i];

    int t  = threadIdx.x;
    int i0 = blockIdx.x * 256;
    int i  = i0 + t;
    float di = 0.f;
    if (i < n) {
        int d = g_cursor[i];
        di = rsqrtf((float)(d + 1));            // +1 self loop
        g_meta[i] = make_float2(di, __int_as_float(d));
    }
    sdinv[t] = di;
    __syncthreads();

    int lane = t & 31;
    int w    = t >> 5;
    int base = i0 + w * 32;
    #pragma unroll 1
    for (int q = 0; q < 32; q++) {
        int node = base + q;
        if (node >= n) break;
        float xv = (lane < 18) ? __ldg(&x[node * 18 + lane]) : 0.f;
        float acc = 0.f;
        #pragma unroll
        for (int k = 0; k < 18; k++) {
            float xk = __shfl_sync(FULL, xv, k);
            acc = fmaf(xk, sW1[k * 32 + lane], acc);
        }
        g_p[node * 32 + lane] = sdinv[w * 32 + q] * acc;
    }
}

// ---- agg1 + relu, store pre-scaled:  g_hs = dinv * relu(di*agg(g_p) + b1) ----

__global__ void __launch_bounds__(256) k_agg1(const float* __restrict__ b1, int n) {
    __shared__ float sb1[32];
    if (threadIdx.x < 32) sb1[threadIdx.x] = b1[threadIdx.x];
    __syncthreads();

    int lane = threadIdx.x & 31;
    int warp = (blockIdx.x * blockDim.x + threadIdx.x) >> 5;
    int nw   = (gridDim.x * blockDim.x) >> 5;
    for (int i = warp; i < n; i += nw) {
        float2 meta = g_meta[i];
        float di = meta.x;
        int cnt  = __float_as_int(meta.y);
        const int4* cp4 = (const int4*)(g_csr + (i << SLOT_SHIFT));
        float s0 = g_p[i * 32 + lane];    // self-loop (already di*xw1)
        float s1 = 0.f, s2 = 0.f, s3 = 0.f;
        int cnt4 = cnt >> 2;
        for (int q = 0; q < cnt4; q++) {
            int4 j = __ldg(cp4 + q);
            s0 += __ldg(&g_p[j.x * 32 + lane]);
            s1 += __ldg(&g_p[j.y * 32 + lane]);
            s2 += __ldg(&g_p[j.z * 32 + lane]);
            s3 += __ldg(&g_p[j.w * 32 + lane]);
        }
        int rem = cnt & 3;
        if (rem) {
            int4 j = __ldg(cp4 + cnt4);
            s0 += __ldg(&g_p[j.x * 32 + lane]);
            if (rem > 1) s1 += __ldg(&g_p[j.y * 32 + lane]);
            if (rem > 2) s2 += __ldg(&g_p[j.z * 32 + lane]);
        }
        float s = (s0 + s1) + (s2 + s3);
        float h = fmaxf(fmaf(di, s, sb1[lane]), 0.f);
        g_hs[i * 32 + lane] = di * h;
    }
}

// gather of one node's 32-dim aggregated input: tt = di * (self + sum(neigh))
__device__ __forceinline__ float gather32(int i, int lane) {
    float2 meta = g_meta[i];
    float di = meta.x;
    int cnt  = __float_as_int(meta.y);
    const int4* cp4 = (const int4*)(g_csr + (i << SLOT_SHIFT));
    float s0 = __ldg(&g_hs[i * 32 + lane]);   // self-loop (already di*h)
    float s1 = 0.f, s2 = 0.f, s3 = 0.f;
    int cnt4 = cnt >> 2;
    for (int q = 0; q < cnt4; q++) {
        int4 j = __ldg(cp4 + q);
        s0 += __ldg(&g_hs[j.x * 32 + lane]);
        s1 += __ldg(&g_hs[j.y * 32 + lane]);
        s2 += __ldg(&g_hs[j.z * 32 + lane]);
        s3 += __ldg(&g_hs[j.w * 32 + lane]);
    }
    int rem = cnt & 3;
    if (rem) {
        int4 j = __ldg(cp4 + cnt4);
        s0 += __ldg(&g_hs[j.x * 32 + lane]);
        if (rem > 1) s1 += __ldg(&g_hs[j.y * 32 + lane]);
        if (rem > 2) s2 += __ldg(&g_hs[j.z * 32 + lane]);
    }
    return di * ((s0 + s1) + (s2 + s3));
}

// ---- agg2: dual-node gather + W2 + relu + FC + log_softmax ----

__global__ void __launch_bounds__(256) k_agg2(const float* __restrict__ W2,
                                              const float* __restrict__ b2,
                                              const float* __restrict__ Wfc,
                                              const float* __restrict__ bfc,
                                              float* __restrict__ out, int n) {
    __shared__ float sW2[32 * 64];
    __shared__ float sWfc[128];
    __shared__ float sb2[64];
    __shared__ float sbfc[2];
    for (int i = threadIdx.x; i < 32 * 64; i += blockDim.x) sW2[i] = W2[i];
    if (threadIdx.x < 128) sWfc[threadIdx.x] = Wfc[threadIdx.x];
    if (threadIdx.x < 64)  sb2[threadIdx.x]  = b2[threadIdx.x];
    if (threadIdx.x < 2)   sbfc[threadIdx.x] = bfc[threadIdx.x];
    __syncthreads();

    int lane = threadIdx.x & 31;
    int q4   = (lane & 15) * 4;     // col group: cols q4..q4+3
    bool isB = lane >= 16;
    // per-lane FC weight registers (hoisted out of the node loop)
    float wf0x = sWfc[q4 * 2],           wf1x = sWfc[(q4 + 1) * 2];
    float wf2x = sWfc[(q4 + 2) * 2],     wf3x = sWfc[(q4 + 3) * 2];
    float wf0y = sWfc[q4 * 2 + 1],       wf1y = sWfc[(q4 + 1) * 2 + 1];
    float wf2y = sWfc[(q4 + 2) * 2 + 1], wf3y = sWfc[(q4 + 3) * 2 + 1];
    float4 bb = *(const float4*)(sb2 + q4);

    int warp = (blockIdx.x * blockDim.x + threadIdx.x) >> 5;
    int nw   = (gridDim.x * blockDim.x) >> 5;
    int npair = (n + 1) >> 1;

    for (int p = warp; p < npair; p += nw) {
        int iA = 2 * p;
        int iB = 2 * p + 1;
        float ttA = gather32(iA, lane);
        float ttB = (iB < n) ? gather32(iB, lane) : 0.f;

        // joint epilogue: lane covers cols q4..q4+3 of node (isB ? B : A)
        float a0 = 0.f, a1 = 0.f, a2 = 0.f, a3 = 0.f;
        #pragma unroll
        for (int l = 0; l < 32; l++) {
            float vA = __shfl_sync(FULL, ttA, l);
            float vB = __shfl_sync(FULL, ttB, l);
            float v  = isB ? vB : vA;
            float4 w = *(const float4*)(sW2 + l * 64 + q4);
            a0 = fmaf(v, w.x, a0);
            a1 = fmaf(v, w.y, a1);
            a2 = fmaf(v, w.z, a2);
            a3 = fmaf(v, w.w, a3);
        }
        float h0 = fmaxf(a0 + bb.x, 0.f);
        float h1 = fmaxf(a1 + bb.y, 0.f);
        float h2 = fmaxf(a2 + bb.z, 0.f);
        float h3 = fmaxf(a3 + bb.w, 0.f);
        float p0 = h0 * wf0x + h1 * wf1x + h2 * wf2x + h3 * wf3x;
        float p1 = h0 * wf0y + h1 * wf1y + h2 * wf2y + h3 * wf3y;
        // reduce within each half-warp (xor offsets stay inside 16-lane halves)
        #pragma unroll
        for (int o = 8; o; o >>= 1) {
            p0 += __shfl_xor_sync(FULL, p0, o);
            p1 += __shfl_xor_sync(FULL, p1, o);
        }
        if (lane == 0 || (lane == 16 && iB < n)) {
            int node = isB ? iB : iA;
            float l0 = p0 + sbfc[0];
            float l1 = p1 + sbfc[1];
            float m  = fmaxf(l0, l1);
            float lse = m + logf(expf(l0 - m) + expf(l1 - m));
            ((float2*)out)[node] = make_float2(l0 - lse, l1 - lse);
        }
    }
}

// ---------------- launch ----------------

extern "C" void kernel_launch(void* const* d_in, const int* in_sizes, int n_in,
                              void* d_out, int out_size) {
    const float* x   = (const float*)d_in[0];
    const int*   ei  = (const int*)d_in[1];
    const float* W1  = (const float*)d_in[2];
    const float* b1  = (const float*)d_in[3];
    const float* W2  = (const float*)d_in[4];
    const float* b2  = (const float*)d_in[5];
    const float* Wfc = (const float*)d_in[6];
    const float* bfc = (const float*)d_in[7];
    float* out = (float*)d_out;

    int n = in_sizes[0] / 18;
    int e = in_sizes[1] / 2;
    const int* src = ei;
    const int* dst = ei + e;

    void* curp = nullptr;
    cudaGetSymbolAddress(&curp, g_cursor);
    cudaMemsetAsync(curp, 0, n * sizeof(int));

    k_scatter<<<(e + 255) / 256, 256>>>(src, dst, e);
    k_meta_xw1<<<(n + 255) / 256, 256>>>(x, W1, n);
    k_agg1<<<1184, 256>>>(b1, n);
    k_agg2<<<1184, 256>>>(W2, b2, Wfc, bfc, out, n);
}

// round 12
// speedup vs baseline: 1.3411x; 1.0844x over previous
#include <cuda_runtime.h>
#include <cuda_bf16.h>
#include <math.h>

// GCN: N<=100000, E<=1280000, 18 -> 32 -> 64 -> 2, log_softmax.
// Slot-CSR (deg<=64, Poisson(12.8)). 4 kernels + 1 memset.
// Half-warp-per-node layout: lane = feature PAIR (f32x2), 16 lanes cover the
// 32-dim row. Gather uses LDG.64 + packed add.rn.f32x2 (half the instructions
// of lane-per-feature, same MLP=4, same wavefronts). agg2 epilogue shares each
// W2 LDS.128 between the two nodes of a warp and accumulates with packed
// fma.rn.f32x2: ~80 warp-inst/node vs 143 in the shuffle-GEMV.

#define MAXN 100000
#define SLOT_SHIFT 6
#define FULL 0xffffffffu

typedef unsigned long long u64;

__device__ int    g_cursor[MAXN];          // zeroed, becomes degree after scatter
__device__ int    g_csr[MAXN << SLOT_SHIFT];
__device__ float2 g_meta[MAXN];            // (dinv, bitcast deg)
__device__ float  g_p [MAXN * 32];         // dinv[i] * (x @ W1)[i]
__device__ float  g_hs[MAXN * 32];         // dinv[i] * relu(layer1)[i]

// ---------------- packed f32x2 helpers ----------------

__device__ __forceinline__ u64 ld2(const float* p) {
    u64 x; asm("ld.global.nc.b64 %0, [%1];" : "=l"(x) : "l"(p)); return x;
}
__device__ __forceinline__ void fadd2(u64& a, u64 x) {
    asm("add.rn.f32x2 %0, %0, %1;" : "+l"(a) : "l"(x));
}
__device__ __forceinline__ void ffma2(u64& d, u64 a, u64 b) {
    asm("fma.rn.f32x2 %0, %1, %2, %0;" : "+l"(d) : "l"(a), "l"(b));
}
__device__ __forceinline__ u64 pack2(float lo, float hi) {
    u64 r; asm("mov.b64 %0, {%1, %2};" : "=l"(r) : "f"(lo), "f"(hi)); return r;
}
__device__ __forceinline__ void unpack2(u64 v, float& lo, float& hi) {
    asm("mov.b64 {%0, %1}, %2;" : "=f"(lo), "=f"(hi) : "l"(v));
}

// half-warp gather: node i_me, lane covers features 2*hl, 2*hl+1.
// cmin = min(cnt of both nodes in the warp) -> unpredicated common loop;
// per-lane scalar tail covers the rest.
__device__ __forceinline__ u64 gather_half(const float* __restrict__ feat,
                                           int i_me, int hl, int cnt, int cmin) {
    const int4* cp4 = (const int4*)(g_csr + (i_me << SLOT_SHIFT));
    u64 a0 = ld2(feat + i_me * 32 + hl * 2);   // self loop (pre-scaled row)
    u64 a1 = 0ull, a2 = 0ull, a3 = 0ull;
    int full4 = cmin >> 2;
    for (int q = 0; q < full4; q++) {
        int4 j = __ldg(cp4 + q);
        fadd2(a0, ld2(feat + j.x * 32 + hl * 2));
        fadd2(a1, ld2(feat + j.y * 32 + hl * 2));
        fadd2(a2, ld2(feat + j.z * 32 + hl * 2));
        fadd2(a3, ld2(feat + j.w * 32 + hl * 2));
    }
    const int* cp = (const int*)cp4;
    for (int k = full4 * 4; k < cnt; k++) {
        int j = __ldg(cp + k);
        fadd2(a0, ld2(feat + j * 32 + hl * 2));
    }
    fadd2(a0, a1); fadd2(a2, a3); fadd2(a0, a2);
    return a0;
}

// ---------------- scatter edges into slot-CSR ----------------

__global__ void k_scatter(const int* __restrict__ src, const int* __restrict__ dst, int e) {
    int i = blockIdx.x * blockDim.x + threadIdx.x;
    if (i < e) {
        int d = dst[i];
        int p = atomicAdd(&g_cursor[d], 1);
        g_csr[(d << SLOT_SHIFT) + p] = src[i];
    }
}

// ---------- meta (dinv,deg) + xw1 pre-scaled: g_p = dinv * (x @ W1) ----------

__global__ void __launch_bounds__(256) k_meta_xw1(const float* __restrict__ x,
                                                  const float* __restrict__ W1, int n) {
    __shared__ float sW1[18 * 32];
    __shared__ float sdinv[256];
    for (int i = threadIdx.x; i < 18 * 32; i += blockDim.x) sW1[i] = W1[i];

    int t  = threadIdx.x;
    int i0 = blockIdx.x * 256;
    int i  = i0 + t;
    float di = 0.f;
    if (i < n) {
        int d = g_cursor[i];
        di = rsqrtf((float)(d + 1));            // +1 self loop
        g_meta[i] = make_float2(di, __int_as_float(d));
    }
    sdinv[t] = di;
    __syncthreads();

    int lane = t & 31;
    int w    = t >> 5;
    int base = i0 + w * 32;
    #pragma unroll 1
    for (int q = 0; q < 32; q++) {
        int node = base + q;
        if (node >= n) break;
        float xv = (lane < 18) ? __ldg(&x[node * 18 + lane]) : 0.f;
        float acc = 0.f;
        #pragma unroll
        for (int k = 0; k < 18; k++) {
            float xk = __shfl_sync(FULL, xv, k);
            acc = fmaf(xk, sW1[k * 32 + lane], acc);
        }
        g_p[node * 32 + lane] = sdinv[w * 32 + q] * acc;
    }
}

// ---- agg1: half-warp per node. g_hs = dinv * relu(di*agg(g_p) + b1) ----

__global__ void __launch_bounds__(256) k_agg1(const float* __restrict__ b1, int n) {
    __shared__ __align__(16) float sb1[32];
    if (threadIdx.x < 32) sb1[threadIdx.x] = b1[threadIdx.x];
    __syncthreads();

    int lane = threadIdx.x & 31;
    int hl   = lane & 15;
    bool isB = lane >= 16;
    int warp = (blockIdx.x * blockDim.x + threadIdx.x) >> 5;
    int nw   = (gridDim.x * blockDim.x) >> 5;
    int npair = (n + 1) >> 1;

    for (int p = warp; p < npair; p += nw) {
        int iA  = 2 * p;
        int iBr = 2 * p + 1;
        int i_me = isB ? ((iBr < n) ? iBr : iA) : iA;
        float2 meta = __ldg(&g_meta[i_me]);
        float di = meta.x;
        int cnt  = __float_as_int(meta.y);
        int cntO = __shfl_xor_sync(FULL, cnt, 16);
        u64 s = gather_half(g_p, i_me, hl, cnt, min(cnt, cntO));
        float s_lo, s_hi;
        unpack2(s, s_lo, s_hi);
        float2 bb = *(const float2*)(sb1 + 2 * hl);
        float h_lo = di * fmaxf(fmaf(di, s_lo, bb.x), 0.f);
        float h_hi = di * fmaxf(fmaf(di, s_hi, bb.y), 0.f);
        *(float2*)(g_hs + i_me * 32 + hl * 2) = make_float2(h_lo, h_hi);
    }
}

// ---- agg2: half-warp gather + shared-LDS W2 epilogue + FC + log_softmax ----

__global__ void __launch_bounds__(256) k_agg2(const float* __restrict__ W2,
                                              const float* __restrict__ b2,
                                              const float* __restrict__ Wfc,
                                              const float* __restrict__ bfc,
                                              float* __restrict__ out, int n) {
    __shared__ __align__(16) float sW2[32 * 64];
    __shared__ __align__(16) float sb2[64];
    __shared__ float sWfc[128];
    __shared__ float sbfc[2];
    for (int i = threadIdx.x; i < 32 * 64; i += blockDim.x) sW2[i] = W2[i];
    if (threadIdx.x < 128) sWfc[threadIdx.x] = Wfc[threadIdx.x];
    if (threadIdx.x < 64)  sb2[threadIdx.x]  = b2[threadIdx.x];
    if (threadIdx.x < 2)   sbfc[threadIdx.x] = bfc[threadIdx.x];
    __syncthreads();

    int lane  = threadIdx.x & 31;
    int hl    = lane & 15;
    int hbase = lane & 16;
    bool isB  = hbase != 0;
    int q4    = hl * 4;                 // this lane owns cols q4..q4+3 of its node

    // hoist per-lane FC weights + bias
    float w0x = sWfc[(q4 + 0) * 2], w0y = sWfc[(q4 + 0) * 2 + 1];
    float w1x = sWfc[(q4 + 1) * 2], w1y = sWfc[(q4 + 1) * 2 + 1];
    float w2x = sWfc[(q4 + 2) * 2], w2y = sWfc[(q4 + 2) * 2 + 1];
    float w3x = sWfc[(q4 + 3) * 2], w3y = sWfc[(q4 + 3) * 2 + 1];
    float4 bb4 = *(const float4*)(sb2 + q4);

    int warp = (blockIdx.x * blockDim.x + threadIdx.x) >> 5;
    int nw   = (gridDim.x * blockDim.x) >> 5;
    int npair = (n + 1) >> 1;

    for (int p = warp; p < npair; p += nw) {
        int iA  = 2 * p;
        int iBr = 2 * p + 1;
        int i_me = isB ? ((iBr < n) ? iBr : iA) : iA;
        float2 meta = __ldg(&g_meta[i_me]);
        float di = meta.x;
        int cnt  = __float_as_int(meta.y);
        int cntO = __shfl_xor_sync(FULL, cnt, 16);
        u64 s = gather_half(g_hs, i_me, hl, cnt, min(cnt, cntO));
        float t_lo, t_hi;
        unpack2(s, t_lo, t_hi);
        t_lo *= di;
        t_hi *= di;

        // epilogue: each l-step broadcasts features (2l, 2l+1) within the half
        // and does 4 packed FMAs; W2 LDS.128 addresses are identical across
        // halves (same l, same q4 pattern) -> dedup'd, serves both nodes.
        u64 c01 = 0ull, c23 = 0ull;     // cols (q4,q4+1), (q4+2,q4+3)
        #pragma unroll
        for (int l = 0; l < 16; l++) {
            float tl = __shfl_sync(FULL, t_lo, hbase + l);
            float th = __shfl_sync(FULL, t_hi, hbase + l);
            ulonglong2 W0 = *(const ulonglong2*)(sW2 + (2 * l) * 64 + q4);
            ulonglong2 W1 = *(const ulonglong2*)(sW2 + (2 * l + 1) * 64 + q4);
            u64 tl2 = pack2(tl, tl);
            u64 th2 = pack2(th, th);
            ffma2(c01, tl2, W0.x);
            ffma2(c23, tl2, W0.y);
            ffma2(c01, th2, W1.x);
            ffma2(c23, th2, W1.y);
        }
        float a0, a1, a2, a3;
        unpack2(c01, a0, a1);
        unpack2(c23, a2, a3);
        float h0 = fmaxf(a0 + bb4.x, 0.f);
        float h1 = fmaxf(a1 + bb4.y, 0.f);
        float h2 = fmaxf(a2 + bb4.z, 0.f);
        float h3 = fmaxf(a3 + bb4.w, 0.f);
        float p0 = h0 * w0x + h1 * w1x + h2 * w2x + h3 * w3x;
        float p1 = h0 * w0y + h1 * w1y + h2 * w2y + h3 * w3y;
        // reduce within each 16-lane half (xor offsets stay inside the half)
        #pragma unroll
        for (int o = 8; o; o >>= 1) {
            p0 += __shfl_xor_sync(FULL, p0, o);
            p1 += __shfl_xor_sync(FULL, p1, o);
        }
        if (hl == 0 && (!isB || iBr < n)) {
            float l0 = p0 + sbfc[0];
            float l1 = p1 + sbfc[1];
            float m  = fmaxf(l0, l1);
            float lse = m + logf(expf(l0 - m) + expf(l1 - m));
            ((float2*)out)[i_me] = make_float2(l0 - lse, l1 - lse);
        }
    }
}

// ---------------- launch ----------------

extern "C" void kernel_launch(void* const* d_in, const int* in_sizes, int n_in,
                              void* d_out, int out_size) {
    const float* x   = (const float*)d_in[0];
    const int*   ei  = (const int*)d_in[1];
    const float* W1  = (const float*)d_in[2];
    const float* b1  = (const float*)d_in[3];
    const float* W2  = (const float*)d_in[4];
    const float* b2  = (const float*)d_in[5];
    const float* Wfc = (const float*)d_in[6];
    const float* bfc = (const float*)d_in[7];
    float* out = (float*)d_out;

    int n = in_sizes[0] / 18;
    int e = in_sizes[1] / 2;
    const int* src = ei;
    const int* dst = ei + e;

    void* curp = nullptr;
    cudaGetSymbolAddress(&curp, g_cursor);
    cudaMemsetAsync(curp, 0, n * sizeof(int));

    k_scatter<<<(e + 255) / 256, 256>>>(src, dst, e);
    k_meta_xw1<<<(n + 255) / 256, 256>>>(x, W1, n);
    k_agg1<<<1184, 256>>>(b1, n);
    k_agg2<<<1184, 256>>>(W2, b2, Wfc, bfc, out, n);
}